// round 9
// baseline (speedup 1.0000x reference)
#include <cuda_runtime.h>

// LSTM recurrence (SLSTM reset='none') + Linear(128->1).
// B=1024, T=2048, IN=16, H=128.
//
// Persistent: 147 CTAs x 512 threads; CTA owns 7 batch rows for all T.
// Thread (q = tid&3, j = tid>>2): ALL 4 gates of hidden unit j over
// K-quarter q (36 of 144 k's: 12 in regs, 24 in smem) in a SINGLE k-sweep
// with 28 persistent f32x2 accumulators (4 gates x 7 rows). Each h chunk
// is loaded once (63 LDS.128) and each smem weight once (24 LDS.128):
// 87 LDS/thread/step vs 111 in R8 -- this kernel is LDS-op-count bound.
// (j&1) swizzle keeps weight LDS.128 conflict-free per 8-lane phase.
// 2-level parity shuffle reduce (24 shfl/step); thread q owns rows
// {q, q+4} (q<3). One __syncthreads per step.

#define T_    2048
#define IN_   16
#define NT    512
#define NCTA  147
#define BB    7
#define BTOT  1024
#define HXROW 144
#define HXBUF (BB * HXROW)                 // 1008 floats
#define WSM_U64 (12 * 2048)                // 24576 u64 = 196608 B
#define SMEM_FLOATS (WSM_U64 * 2 + 2 * HXBUF + 128)   // 51296
#define SMEM_BYTES  (SMEM_FLOATS * 4)                  // 205184

typedef unsigned long long u64;

__device__ __forceinline__ void ffma2(u64 &d, u64 a, u64 b) {
    asm("fma.rn.f32x2 %0, %1, %2, %0;" : "+l"(d) : "l"(a), "l"(b));
}
__device__ __forceinline__ float2 unpk(u64 v) {
    float2 r;
    asm("mov.b64 {%0, %1}, %2;" : "=f"(r.x), "=f"(r.y) : "l"(v));
    return r;
}
__device__ __forceinline__ float ex2a(float x) {
    float y; asm("ex2.approx.f32 %0, %1;" : "=f"(y) : "f"(x)); return y;
}
__device__ __forceinline__ float rcpa(float x) {
    float y; asm("rcp.approx.f32 %0, %1;" : "=f"(y) : "f"(x)); return y;
}
__device__ __forceinline__ float sig_(float x) {
    return rcpa(1.0f + ex2a(-1.4426950408889634f * x));
}
__device__ __forceinline__ float tanh_(float x) {
    return 2.0f * rcpa(1.0f + ex2a(-2.8853900817779268f * x)) - 1.0f;
}

extern "C" __global__ void __launch_bounds__(NT, 1)
slstm_kernel(const float* __restrict__ x, const float* __restrict__ W_ih,
             const float* __restrict__ W_hh, const float* __restrict__ b_ih,
             const float* __restrict__ b_hh, const float* __restrict__ fc_w,
             const float* __restrict__ fc_b, float* __restrict__ out)
{
    extern __shared__ float sm[];
    float* Wsm = sm;                          // 12 pl x [j][q][half][gg] u64
    float* hx  = sm + WSM_U64 * 2;            // 2 x [7][144]
    float* fcw = sm + WSM_U64 * 2 + 2 * HXBUF;

    const int tid = threadIdx.x;
    const int q   = tid & 3;                  // K quarter
    const int j   = tid >> 2;                 // hidden unit 0..127
    const int kb  = q & 1;
    const int kt  = (q >> 1) & 1;
    const int bbase = blockIdx.x * BB;

    // ---- prologue: SMEM weights (smem pairs 6..17 of each quarter) ----
    // u64 idx s = pl*2048 + j*16 + q*4 + half*2 + gg, half = gp ^ (j&1),
    // gate g = 2*gp + gg, pair: k0 = q*36 + 12 + 2*pl.  (verified R7/R8)
    for (int s = tid; s < WSM_U64; s += NT) {
        const int gg   = s & 1;
        const int half = (s >> 1) & 1;
        const int qq   = (s >> 2) & 3;
        const int jj   = (s >> 4) & 127;
        const int pl   = s >> 11;
        const int gp   = half ^ (jj & 1);
        const int g    = 2 * gp + gg;
        const int k0   = qq * 36 + 12 + 2 * pl;
        const int row  = g * 128 + jj;
        float w0, w1;
        if (k0 < 128) {
            w0 = W_hh[row * 128 + k0];
            w1 = W_hh[row * 128 + k0 + 1];
        } else {
            w0 = W_ih[row * 16 + (k0 - 128)];
            w1 = W_ih[row * 16 + (k0 - 127)];
        }
        Wsm[2 * s]     = w0;
        Wsm[2 * s + 1] = w1;
    }
    if (tid < 128) fcw[tid] = fc_w[tid];

    // ---- register weights: pairs 0..5 of this quarter, all 4 gates ----
    u64 wr[4][6];
#pragma unroll
    for (int g = 0; g < 4; ++g) {
        const int row = g * 128 + j;
#pragma unroll
        for (int i = 0; i < 6; ++i)
            wr[g][i] = *(const u64*)&W_hh[row * 128 + q * 36 + 2 * i];
    }
    float bias[4];
#pragma unroll
    for (int g = 0; g < 4; ++g)
        bias[g] = b_ih[g * 128 + j] + b_hh[g * 128 + j];

    // ---- init: h0 = 0, x(0) staged ----
    for (int s = tid; s < BB * 128; s += NT) {
        const int b = s >> 7, k = s & 127;
        hx[b * HXROW + k] = 0.0f;
    }
    {
        const int b = tid >> 4, i = tid & 15;
        if (tid < BB * IN_)
            hx[b * HXROW + 128 + i] =
                (bbase + b < BTOT) ? x[(bbase + b) * (T_ * IN_) + i] : 0.0f;
    }
    float c0 = 0.0f, c1 = 0.0f;               // rows q and q+4 (q<3)
    __syncthreads();

    const u64* Wu = (const u64*)Wsm;
    const int xb = tid >> 4, xi = tid & 15;
    const bool xok = (tid < BB * IN_) && (bbase + xb < BTOT);
    const int wbase = j * 16 + q * 4;                 // weight addr component
    const int h0off = ( (j & 1)      ) << 1;          // gates 0,1 slot
    const int h1off = ( (j & 1) ^ 1  ) << 1;          // gates 2,3 slot

    int cur = 0;
    for (int t = 0; t < T_; ++t) {
        float xv = 0.0f;
        const bool doX = xok && (t + 1 < T_);
        if (doX)
            xv = x[(bbase + xb) * (T_ * IN_) + (t + 1) * IN_ + xi];

        const float* hb = hx + cur * HXBUF + q * 36;  // quarter base folded in
        float* hn = hx + (cur ^ 1) * HXBUF;

        // ---- single k-sweep, persistent acc[4 gates][7 rows] ----
        u64 acc[4][7];
#pragma unroll
        for (int g = 0; g < 4; ++g)
#pragma unroll
            for (int r = 0; r < 7; ++r) acc[g][r] = 0ull;

        // reg-weight section: 3 chunks (6 pairs), h loaded once per row
#pragma unroll
        for (int cc = 0; cc < 3; ++cc) {
#pragma unroll
            for (int r = 0; r < 7; ++r) {
                const ulonglong2 hv =
                    *(const ulonglong2*)&hb[r * HXROW + 4 * cc];
#pragma unroll
                for (int g = 0; g < 4; ++g) {
                    ffma2(acc[g][r], wr[g][2 * cc],     hv.x);
                    ffma2(acc[g][r], wr[g][2 * cc + 1], hv.y);
                }
            }
        }

        // smem-weight section: 6 iters x 2 pairs, each weight loaded ONCE
#pragma unroll
        for (int m = 0; m < 6; ++m) {
            const u64* bp = Wu + (2 * m) * 2048 + wbase;
            const ulonglong2 w0A = *(const ulonglong2*)(bp + h0off);
            const ulonglong2 w0B = *(const ulonglong2*)(bp + h1off);
            const ulonglong2 w1A = *(const ulonglong2*)(bp + 2048 + h0off);
            const ulonglong2 w1B = *(const ulonglong2*)(bp + 2048 + h1off);
#pragma unroll
            for (int r = 0; r < 7; ++r) {
                const ulonglong2 hv =
                    *(const ulonglong2*)&hb[r * HXROW + 12 + 4 * m];
                ffma2(acc[0][r], w0A.x, hv.x);
                ffma2(acc[1][r], w0A.y, hv.x);
                ffma2(acc[2][r], w0B.x, hv.x);
                ffma2(acc[3][r], w0B.y, hv.x);
                ffma2(acc[0][r], w1A.x, hv.y);
                ffma2(acc[1][r], w1A.y, hv.y);
                ffma2(acc[2][r], w1B.x, hv.y);
                ffma2(acc[3][r], w1B.y, hv.y);
            }
        }

        // ---- reduce across q-threads (verified R7 scheme, per gate) ----
        float gvq[4], gvq4[4];     // row q, row q+4
#pragma unroll
        for (int g = 0; g < 4; ++g) {
            float s[7];
#pragma unroll
            for (int p = 0; p < 7; ++p) {
                const float2 a = unpk(acc[g][p]);
                s[p] = a.x + a.y;
            }
            // level 1 (xor 1): keep rows with (p&1)==kb
#pragma unroll
            for (int sl = 0; sl < 4; ++sl) {
                const float pay = kb ? s[2 * sl]
                                     : s[(2 * sl + 1 > 6) ? 6 : 2 * sl + 1];
                const float rc = __shfl_xor_sync(0xffffffffu, pay, 1);
                s[2 * sl] += kb ? 0.0f : rc;
                if (sl < 3) s[2 * sl + 1] += kb ? rc : 0.0f;
            }
            // level 2 (xor 2): my rows {q, q+4}, partner rows {q^2, (q^2)+4}
            const float vm0 = kt ? (kb ? s[3] : s[2]) : (kb ? s[1] : s[0]);
            const float vm1 = kt ? (kb ? s[0] : s[6]) : (kb ? s[5] : s[4]);
            const float vp0 = kt ? (kb ? s[1] : s[0]) : (kb ? s[3] : s[2]);
            const float vp1 = kt ? (kb ? s[5] : s[4]) : (kb ? s[0] : s[6]);
            gvq[g]  = vm0 + __shfl_xor_sync(0xffffffffu, vp0, 2) + bias[g];
            gvq4[g] = vm1 + __shfl_xor_sync(0xffffffffu, vp1, 2) + bias[g];
        }

        // ---- activations: rows q and q+4 (q<3) ----
        {
            const float cn = sig_(gvq[1]) * c0 + sig_(gvq[0]) * tanh_(gvq[2]);
            c0 = cn;
            hn[q * HXROW + j] = sig_(gvq[3]) * tanh_(cn);
        }
        {
            const float cn = sig_(gvq4[1]) * c1 + sig_(gvq4[0]) * tanh_(gvq4[2]);
            const float hv = sig_(gvq4[3]) * tanh_(cn);
            if (q < 3) {
                c1 = cn;
                hn[(q + 4) * HXROW + j] = hv;
            }
        }
        if (doX)
            hn[xb * HXROW + 128 + xi] = xv;

        __syncthreads();
        cur ^= 1;
    }

    // ---- output: out[b] = h_T[b] . fc_w + fc_b ----
    if (tid < BB && bbase + tid < BTOT) {
        const float* hbf = hx + cur * HXBUF + tid * HXROW;
        float s = fc_b[0];
#pragma unroll 8
        for (int k = 0; k < 128; ++k) s += hbf[k] * fcw[k];
        out[bbase + tid] = s;
    }
}

extern "C" void kernel_launch(void* const* d_in, const int* in_sizes, int n_in,
                              void* d_out, int out_size)
{
    const float* x    = (const float*)d_in[0];
    const float* W_ih = (const float*)d_in[1];
    const float* W_hh = (const float*)d_in[2];
    const float* b_ih = (const float*)d_in[3];
    const float* b_hh = (const float*)d_in[4];
    const float* fc_w = (const float*)d_in[5];
    const float* fc_b = (const float*)d_in[6];
    float* out = (float*)d_out;

    cudaFuncSetAttribute(slstm_kernel,
                         cudaFuncAttributeMaxDynamicSharedMemorySize, SMEM_BYTES);
    slstm_kernel<<<NCTA, NT, SMEM_BYTES>>>(x, W_ih, W_hh, b_ih, b_hh,
                                           fc_w, fc_b, out);
}

// round 11
// speedup vs baseline: 1.4672x; 1.4672x over previous
#include <cuda_runtime.h>

// LSTM recurrence (SLSTM reset='none') + Linear(128->1).
// B=1024, T=2048, IN=16, H=128.
//
// Chunked two-kernel pipeline (4 chunks x 512 timesteps, single 1-GiB xg
// buffer to stay inside aarch64 .bss relocation range):
//   per chunk: xg_kernel precomputes xg[tloc][b][j*4+g] = x.W_ih^T + biases
//   (time-parallel, DRAM-streamed); slstm_kernel runs 512 recurrent steps.
//   h/c state carried between chunk launches via 1 MB __device__ arrays;
//   chunk 0 zero-inits state (deterministic across graph replays).
//
// slstm_kernel: persistent 147 CTAs x 512 threads; CTA owns 7 batch rows.
// Thread (q = tid&3, j = tid>>2): ALL 4 gates of unit j over K-quarter q
// (32 of 128 h-k's: 8 in regs, 24 in smem) in a SINGLE k-sweep (weights
// read once/SM/step; wr is 32 regs so acc[4][7] fits unspilled). xg
// streamed from DRAM (2 LDG.128/thread/step, prefetched early). h stored
// with 36-stride quarter padding (HXROW=144) for conflict-free LDS.
// Verified 2-level parity shuffle reduce; thread q owns rows {q, q+4}
// (q<3). One __syncthreads per step.

#define T_    2048
#define TCH   512                          // timesteps per chunk
#define NCH   4
#define IN_   16
#define NT    512
#define NCTA  147
#define BB    7
#define BTOT  1024
#define HXROW 144
#define HXBUF (BB * HXROW)                 // 1008 floats
#define WSM_U64 (12 * 2048)                // 24576 u64 = 196608 B
#define SMEM_FLOATS (WSM_U64 * 2 + 2 * HXBUF + 128)   // 51296
#define SMEM_BYTES  (SMEM_FLOATS * 4)                  // 205184

typedef unsigned long long u64;

// Scratch: one xg chunk buffer (1 GiB) + h/c carry state (1 MB).
__device__ float xgbuf[(size_t)TCH * 1024 * 512];
__device__ float h_state[BTOT * 128];
__device__ float c_state[BTOT * 128];

__device__ __forceinline__ void ffma2(u64 &d, u64 a, u64 b) {
    asm("fma.rn.f32x2 %0, %1, %2, %0;" : "+l"(d) : "l"(a), "l"(b));
}
__device__ __forceinline__ float2 unpk(u64 v) {
    float2 r;
    asm("mov.b64 {%0, %1}, %2;" : "=f"(r.x), "=f"(r.y) : "l"(v));
    return r;
}
__device__ __forceinline__ float ex2a(float x) {
    float y; asm("ex2.approx.f32 %0, %1;" : "=f"(y) : "f"(x)); return y;
}
__device__ __forceinline__ float rcpa(float x) {
    float y; asm("rcp.approx.f32 %0, %1;" : "=f"(y) : "f"(x)); return y;
}
__device__ __forceinline__ float sig_(float x) {
    return rcpa(1.0f + ex2a(-1.4426950408889634f * x));
}
__device__ __forceinline__ float tanh_(float x) {
    return 2.0f * rcpa(1.0f + ex2a(-2.8853900817779268f * x)) - 1.0f;
}

// ======================= xg precompute (per chunk) =======================
// Block handles 64 consecutive tloc of one batch row b.
// blockIdx: b = bid >> 3, tl0 = (bid & 7) * 64.  tid = j*4+g.
#define XG_TB 64
extern "C" __global__ void __launch_bounds__(NT, 2)
xg_kernel(const float* __restrict__ x, const float* __restrict__ W_ih,
          const float* __restrict__ b_ih, const float* __restrict__ b_hh,
          int t0)
{
    __shared__ float xs[XG_TB * IN_];
    const int tid = threadIdx.x;
    const int g = tid & 3;
    const int j = tid >> 2;
    const int b   = blockIdx.x >> 3;
    const int tl0 = (blockIdx.x & 7) * XG_TB;

    const float* wrow = W_ih + (g * 128 + j) * IN_;
    u64 w[8];
#pragma unroll
    for (int i = 0; i < 8; ++i) w[i] = *(const u64*)&wrow[2 * i];
    const float bb = b_ih[g * 128 + j] + b_hh[g * 128 + j];

    const size_t xbase = ((size_t)b * T_ + t0 + tl0) * IN_;
    for (int i = tid; i < XG_TB * IN_; i += NT)
        xs[i] = x[xbase + i];
    __syncthreads();

#pragma unroll 4
    for (int s = 0; s < XG_TB; ++s) {
        u64 acc = 0ull;
#pragma unroll
        for (int i = 0; i < 8; ++i)
            ffma2(acc, w[i], *(const u64*)&xs[s * IN_ + 2 * i]);
        const float2 a = unpk(acc);
        xgbuf[((size_t)(tl0 + s) * 1024 + b) * 512 + tid] = a.x + a.y + bb;
    }
}

// ======================= recurrent kernel (per chunk) =======================
extern "C" __global__ void __launch_bounds__(NT, 1)
slstm_kernel(const float* __restrict__ W_hh, const float* __restrict__ fc_w,
             const float* __restrict__ fc_b, float* __restrict__ out, int t0)
{
    extern __shared__ float sm[];
    float* Wsm = sm;                          // 12 pl x [j][q][half][gg] u64
    float* hx  = sm + WSM_U64 * 2;            // 2 x [7][144]
    float* fcw = sm + WSM_U64 * 2 + 2 * HXBUF;

    const int tid = threadIdx.x;
    const int q   = tid & 3;                  // K quarter (32 h-units)
    const int j   = tid >> 2;                 // hidden unit 0..127
    const int kb  = q & 1;
    const int kt  = (q >> 1) & 1;
    const int bbase = blockIdx.x * BB;

    // ---- prologue: SMEM weights, h-k's 8..31 of each quarter ----
    for (int s = tid; s < WSM_U64; s += NT) {
        const int gg   = s & 1;
        const int half = (s >> 1) & 1;
        const int qq   = (s >> 2) & 3;
        const int jj   = (s >> 4) & 127;
        const int pl   = s >> 11;
        const int gp   = half ^ (jj & 1);
        const int g    = 2 * gp + gg;
        const int k0   = qq * 32 + 8 + 2 * pl;
        const int row  = g * 128 + jj;
        Wsm[2 * s]     = W_hh[row * 128 + k0];
        Wsm[2 * s + 1] = W_hh[row * 128 + k0 + 1];
    }
    if (tid < 128) fcw[tid] = fc_w[tid];

    // ---- register weights: h-k's q*32 .. q*32+7 (4 pairs x 4 gates) ----
    u64 wr[4][4];
#pragma unroll
    for (int g = 0; g < 4; ++g) {
        const int row = g * 128 + j;
#pragma unroll
        for (int i = 0; i < 4; ++i)
            wr[g][i] = *(const u64*)&W_hh[row * 128 + q * 32 + 2 * i];
    }

    const int jsw = 36 * (j >> 5) + (j & 31);     // padded unit offset
    const int b0 = bbase + q;                     // owned row 1
    const int b1 = bbase + q + 4;                 // owned row 2 (q<3)
    const bool v0 = (b0 < BTOT);
    const bool v1 = (q < 3) && (b1 < BTOT);

    // ---- state restore (chunk 0: zeros; else carry from h/c_state) ----
    float c0 = 0.0f, c1 = 0.0f;
    if (t0 == 0) {
        for (int s = tid; s < 2 * HXBUF; s += NT) hx[s] = 0.0f;
    } else {
        if (v0) {
            hx[q * HXROW + jsw] = h_state[b0 * 128 + j];
            c0 = c_state[b0 * 128 + j];
        } else hx[q * HXROW + jsw] = 0.0f;
        if (q < 3) {
            if (v1) {
                hx[(q + 4) * HXROW + jsw] = h_state[b1 * 128 + j];
                c1 = c_state[b1 * 128 + j];
            } else hx[(q + 4) * HXROW + jsw] = 0.0f;
        }
    }
    __syncthreads();

    const u64* Wu = (const u64*)Wsm;
    const int wbase = j * 16 + q * 4;
    const int h0off = ( (j & 1)      ) << 1;  // gates 0,1 slot
    const int h1off = ( (j & 1) ^ 1  ) << 1;  // gates 2,3 slot
    const size_t xoff0 = (size_t)(v0 ? b0 : BTOT - 1) * 512 + 4 * j;
    const size_t xoff1 = (size_t)((q < 3 && b1 < BTOT) ? b1 : BTOT - 1) * 512
                         + 4 * j;

    int cur = 0;
    for (int tl = 0; tl < TCH; ++tl) {
        // prefetch this step's xg (consumed after the FMA sweep)
        const float* xgp = xgbuf + (size_t)tl * 1024 * 512;
        const float4 xga = *(const float4*)(xgp + xoff0);
        const float4 xgb = *(const float4*)(xgp + xoff1);

        const float* hb = hx + cur * HXBUF + q * 36;  // quarter base folded
        float* hn = hx + (cur ^ 1) * HXBUF;

        // ---- single k-sweep, persistent acc[4 gates][7 rows] ----
        u64 acc[4][7];
#pragma unroll
        for (int g = 0; g < 4; ++g)
#pragma unroll
            for (int r = 0; r < 7; ++r) acc[g][r] = 0ull;

        // reg-weight section: 2 chunks (4 pairs)
#pragma unroll
        for (int cc = 0; cc < 2; ++cc) {
#pragma unroll
            for (int r = 0; r < 7; ++r) {
                const ulonglong2 hv =
                    *(const ulonglong2*)&hb[r * HXROW + 4 * cc];
#pragma unroll
                for (int g = 0; g < 4; ++g) {
                    ffma2(acc[g][r], wr[g][2 * cc],     hv.x);
                    ffma2(acc[g][r], wr[g][2 * cc + 1], hv.y);
                }
            }
        }

        // smem-weight section: 6 iters x 2 pair-layers, each weight ONCE
#pragma unroll
        for (int m = 0; m < 6; ++m) {
            const u64* bp = Wu + (2 * m) * 2048 + wbase;
            const ulonglong2 w0A = *(const ulonglong2*)(bp + h0off);
            const ulonglong2 w0B = *(const ulonglong2*)(bp + h1off);
            const ulonglong2 w1A = *(const ulonglong2*)(bp + 2048 + h0off);
            const ulonglong2 w1B = *(const ulonglong2*)(bp + 2048 + h1off);
#pragma unroll
            for (int r = 0; r < 7; ++r) {
                const ulonglong2 hv =
                    *(const ulonglong2*)&hb[r * HXROW + 8 + 4 * m];
                ffma2(acc[0][r], w0A.x, hv.x);
                ffma2(acc[1][r], w0A.y, hv.x);
                ffma2(acc[2][r], w0B.x, hv.x);
                ffma2(acc[3][r], w0B.y, hv.x);
                ffma2(acc[0][r], w1A.x, hv.y);
                ffma2(acc[1][r], w1A.y, hv.y);
                ffma2(acc[2][r], w1B.x, hv.y);
                ffma2(acc[3][r], w1B.y, hv.y);
            }
        }

        // ---- reduce across q-threads (verified parity scheme) ----
        const float xgaA[4] = {xga.x, xga.y, xga.z, xga.w};
        const float xgbA[4] = {xgb.x, xgb.y, xgb.z, xgb.w};
        float gvq[4], gvq4[4];
#pragma unroll
        for (int g = 0; g < 4; ++g) {
            float s[7];
#pragma unroll
            for (int p = 0; p < 7; ++p) {
                const float2 a = unpk(acc[g][p]);
                s[p] = a.x + a.y;
            }
            // level 1 (xor 1): keep rows with (p&1)==kb
#pragma unroll
            for (int sl = 0; sl < 4; ++sl) {
                const float pay = kb ? s[2 * sl]
                                     : s[(2 * sl + 1 > 6) ? 6 : 2 * sl + 1];
                const float rc = __shfl_xor_sync(0xffffffffu, pay, 1);
                s[2 * sl] += kb ? 0.0f : rc;
                if (sl < 3) s[2 * sl + 1] += kb ? rc : 0.0f;
            }
            // level 2 (xor 2)
            const float vm0 = kt ? (kb ? s[3] : s[2]) : (kb ? s[1] : s[0]);
            const float vm1 = kt ? (kb ? s[0] : s[6]) : (kb ? s[5] : s[4]);
            const float vp0 = kt ? (kb ? s[1] : s[0]) : (kb ? s[3] : s[2]);
            const float vp1 = kt ? (kb ? s[5] : s[4]) : (kb ? s[0] : s[6]);
            gvq[g]  = vm0 + __shfl_xor_sync(0xffffffffu, vp0, 2) + xgaA[g];
            gvq4[g] = vm1 + __shfl_xor_sync(0xffffffffu, vp1, 2) + xgbA[g];
        }

        // ---- activations: rows q and q+4 (q<3) ----
        {
            const float cn = sig_(gvq[1]) * c0 + sig_(gvq[0]) * tanh_(gvq[2]);
            c0 = cn;
            hn[q * HXROW + jsw] = sig_(gvq[3]) * tanh_(cn);
        }
        {
            const float cn = sig_(gvq4[1]) * c1 + sig_(gvq4[0]) * tanh_(gvq4[2]);
            const float hv = sig_(gvq4[3]) * tanh_(cn);
            if (q < 3) {
                c1 = cn;
                hn[(q + 4) * HXROW + jsw] = hv;
            }
        }

        __syncthreads();
        cur ^= 1;
    }

    if (t0 + TCH < T_) {
        // ---- state save for next chunk ----
        if (v0) {
            h_state[b0 * 128 + j] = hx[cur * HXBUF + q * HXROW + jsw];
            c_state[b0 * 128 + j] = c0;
        }
        if (v1) {
            h_state[b1 * 128 + j] = hx[cur * HXBUF + (q + 4) * HXROW + jsw];
            c_state[b1 * 128 + j] = c1;
        }
    } else {
        // ---- final chunk: out[b] = h_T[b] . fc_w + fc_b ----
        if (tid < BB && bbase + tid < BTOT) {
            const float* hbf = hx + cur * HXBUF + tid * HXROW;
            float s = fc_b[0];
#pragma unroll 8
            for (int k = 0; k < 128; ++k)
                s += hbf[36 * (k >> 5) + (k & 31)] * fcw[k];
            out[bbase + tid] = s;
        }
    }
}

extern "C" void kernel_launch(void* const* d_in, const int* in_sizes, int n_in,
                              void* d_out, int out_size)
{
    const float* x    = (const float*)d_in[0];
    const float* W_ih = (const float*)d_in[1];
    const float* W_hh = (const float*)d_in[2];
    const float* b_ih = (const float*)d_in[3];
    const float* b_hh = (const float*)d_in[4];
    const float* fc_w = (const float*)d_in[5];
    const float* fc_b = (const float*)d_in[6];
    float* out = (float*)d_out;

    cudaFuncSetAttribute(slstm_kernel,
                         cudaFuncAttributeMaxDynamicSharedMemorySize, SMEM_BYTES);

    for (int ch = 0; ch < NCH; ++ch) {
        const int t0 = ch * TCH;
        xg_kernel<<<1024 * (TCH / XG_TB), NT>>>(x, W_ih, b_ih, b_hh, t0);
        slstm_kernel<<<NCTA, NT, SMEM_BYTES>>>(W_hh, fc_w, fc_b, out, t0);
    }
}

// round 12
// speedup vs baseline: 1.6340x; 1.1137x over previous
#include <cuda_runtime.h>

// LSTM recurrence (SLSTM reset='none') + Linear(128->1).
// B=1024, T=2048, IN=16, H=128.
//
// Single persistent kernel: 147 CTAs x 512 threads; CTA owns 7 batch rows.
// Thread (q = tid&3, j = tid>>2): ALL 4 gates of unit j over K-quarter q
// (36 of 144 k's) in a SINGLE k-sweep with acc[4][7] (56 regs).
// Weight placement (the R9/R11 spill fix):
//   - 24 k's/quarter in SMEM (R8-verified layout, read once per SM per step)
//   - 12 k's/quarter via LDG from a 96KB prepacked global scratch that is
//     L2-resident (every SM reads it every step); issued in two waves
//     (4 then 8 LDG.128) consumed 3 smem-plane iterations later, so
//     transient regs stay <= 32 and L2 latency (~234cyc) is hidden.
//   -> NO register-resident weights: persistent regs ~76, peak ~120.
// LDS/thread/step = 63 h + 24 w = 87 (LDS.128 count is the crossbar
// currency: ~4 cyc each regardless of broadcast). x stays in-loop (k's
// 128..143). Verified 2-level parity shuffle reduce; thread q owns rows
// {q, q+4} (q<3). One __syncthreads per step.

#define T_    2048
#define IN_   16
#define NT    512
#define NCTA  147
#define BB    7
#define BTOT  1024
#define HXROW 144
#define HXBUF (BB * HXROW)                 // 1008 floats
#define WSM_U64 (12 * 2048)                // 24576 u64 = 196608 B
#define SMEM_FLOATS (WSM_U64 * 2 + 2 * HXBUF + 128)   // 51296
#define SMEM_BYTES  (SMEM_FLOATS * 4)                  // 205184

typedef unsigned long long u64;

// Prepacked LDG weights: 12 chunk-slots x 512 threads, float4 each = 96KB.
// chunk c = cc*4 + g (cc in 0..2, g in 0..3); slot = tid (= j*4+q).
// Entry = W_hh[row(g,j)][q*36 + 4*cc .. +3].
__device__ float4 wgpack[12 * 512];

__device__ __forceinline__ void ffma2(u64 &d, u64 a, u64 b) {
    asm("fma.rn.f32x2 %0, %1, %2, %0;" : "+l"(d) : "l"(a), "l"(b));
}
__device__ __forceinline__ float2 unpk(u64 v) {
    float2 r;
    asm("mov.b64 {%0, %1}, %2;" : "=f"(r.x), "=f"(r.y) : "l"(v));
    return r;
}
__device__ __forceinline__ float ex2a(float x) {
    float y; asm("ex2.approx.f32 %0, %1;" : "=f"(y) : "f"(x)); return y;
}
__device__ __forceinline__ float rcpa(float x) {
    float y; asm("rcp.approx.f32 %0, %1;" : "=f"(y) : "f"(x)); return y;
}
__device__ __forceinline__ float sig_(float x) {
    return rcpa(1.0f + ex2a(-1.4426950408889634f * x));
}
__device__ __forceinline__ float tanh_(float x) {
    return 2.0f * rcpa(1.0f + ex2a(-2.8853900817779268f * x)) - 1.0f;
}

extern "C" __global__ void __launch_bounds__(NT, 1)
slstm_kernel(const float* __restrict__ x, const float* __restrict__ W_ih,
             const float* __restrict__ W_hh, const float* __restrict__ b_ih,
             const float* __restrict__ b_hh, const float* __restrict__ fc_w,
             const float* __restrict__ fc_b, float* __restrict__ out)
{
    extern __shared__ float sm[];
    float* Wsm = sm;                          // 12 pl x [j][q][half][gg] u64
    float* hx  = sm + WSM_U64 * 2;            // 2 x [7][144]
    float* fcw = sm + WSM_U64 * 2 + 2 * HXBUF;

    const int tid = threadIdx.x;
    const int q   = tid & 3;                  // K quarter
    const int j   = tid >> 2;                 // hidden unit 0..127
    const int kb  = q & 1;
    const int kt  = (q >> 1) & 1;
    const int bbase = blockIdx.x * BB;

    // ---- prepack LDG weights (idempotent across CTAs; own writes are
    //      visible to this CTA after __syncthreads) ----
    for (int s = tid; s < 12 * 512; s += NT) {
        const int slot = s & 511;
        const int c    = s >> 9;
        const int jj   = slot >> 2;
        const int qq   = slot & 3;
        const int cc   = c >> 2;
        const int g    = c & 3;
        const int row  = g * 128 + jj;
        const int k0   = qq * 36 + 4 * cc;    // 0..107+8 < 128: always W_hh
        wgpack[s] = *(const float4*)&W_hh[row * 128 + k0];
    }

    // ---- prologue: SMEM weights (k's 12..35 of each quarter) ----
    // u64 idx s = pl*2048 + j*16 + q*4 + half*2 + gg, half = gp ^ (j&1),
    // gate g = 2*gp + gg, pair: k0 = q*36 + 12 + 2*pl.  (verified R7/R8)
    for (int s = tid; s < WSM_U64; s += NT) {
        const int gg   = s & 1;
        const int half = (s >> 1) & 1;
        const int qq   = (s >> 2) & 3;
        const int jj   = (s >> 4) & 127;
        const int pl   = s >> 11;
        const int gp   = half ^ (jj & 1);
        const int g    = 2 * gp + gg;
        const int k0   = qq * 36 + 12 + 2 * pl;
        const int row  = g * 128 + jj;
        float w0, w1;
        if (k0 < 128) {
            w0 = W_hh[row * 128 + k0];
            w1 = W_hh[row * 128 + k0 + 1];
        } else {
            w0 = W_ih[row * 16 + (k0 - 128)];
            w1 = W_ih[row * 16 + (k0 - 127)];
        }
        Wsm[2 * s]     = w0;
        Wsm[2 * s + 1] = w1;
    }
    if (tid < 128) fcw[tid] = fc_w[tid];

    float bias[4];
#pragma unroll
    for (int g = 0; g < 4; ++g)
        bias[g] = b_ih[g * 128 + j] + b_hh[g * 128 + j];

    // ---- init: h0 = 0, x(0) staged ----
    for (int s = tid; s < BB * 128; s += NT) {
        const int b = s >> 7, k = s & 127;
        hx[b * HXROW + k] = 0.0f;
    }
    {
        const int b = tid >> 4, i = tid & 15;
        if (tid < BB * IN_)
            hx[b * HXROW + 128 + i] =
                (bbase + b < BTOT) ? x[(bbase + b) * (T_ * IN_) + i] : 0.0f;
    }
    float c0 = 0.0f, c1 = 0.0f;               // rows q and q+4 (q<3)
    __syncthreads();

    const u64* Wu = (const u64*)Wsm;
    const int xb = tid >> 4, xi = tid & 15;
    const bool xok = (tid < BB * IN_) && (bbase + xb < BTOT);
    const int wbase = j * 16 + q * 4;
    const int h0off = ( (j & 1)      ) << 1;  // gates 0,1 slot
    const int h1off = ( (j & 1) ^ 1  ) << 1;  // gates 2,3 slot
    const ulonglong2* wgp = (const ulonglong2*)wgpack + tid;  // +c*512 per chunk

    int cur = 0;
    for (int t = 0; t < T_; ++t) {
        float xv = 0.0f;
        const bool doX = xok && (t + 1 < T_);
        if (doX)
            xv = x[(bbase + xb) * (T_ * IN_) + (t + 1) * IN_ + xi];

        const float* hb = hx + cur * HXBUF + q * 36;  // quarter base folded
        float* hn = hx + (cur ^ 1) * HXBUF;

        u64 acc[4][7];
#pragma unroll
        for (int g = 0; g < 4; ++g)
#pragma unroll
            for (int r = 0; r < 7; ++r) acc[g][r] = 0ull;

        // ---- wave A: LDG weights for cc=0 (4 gates) ----
        ulonglong2 wA[4];
#pragma unroll
        for (int g = 0; g < 4; ++g) wA[g] = wgp[g * 512];

        // ---- smem planes 0..2 (hides wave A latency) ----
#pragma unroll
        for (int m = 0; m < 3; ++m) {
            const u64* bp = Wu + (2 * m) * 2048 + wbase;
            const ulonglong2 w0A = *(const ulonglong2*)(bp + h0off);
            const ulonglong2 w0B = *(const ulonglong2*)(bp + h1off);
            const ulonglong2 w1A = *(const ulonglong2*)(bp + 2048 + h0off);
            const ulonglong2 w1B = *(const ulonglong2*)(bp + 2048 + h1off);
#pragma unroll
            for (int r = 0; r < 7; ++r) {
                const ulonglong2 hv =
                    *(const ulonglong2*)&hb[r * HXROW + 12 + 4 * m];
                ffma2(acc[0][r], w0A.x, hv.x);
                ffma2(acc[1][r], w0A.y, hv.x);
                ffma2(acc[2][r], w0B.x, hv.x);
                ffma2(acc[3][r], w0B.y, hv.x);
                ffma2(acc[0][r], w1A.x, hv.y);
                ffma2(acc[1][r], w1A.y, hv.y);
                ffma2(acc[2][r], w1B.x, hv.y);
                ffma2(acc[3][r], w1B.y, hv.y);
            }
        }

        // ---- consume wave A (cc=0), issue wave B (cc=1,2) ----
        ulonglong2 wB[8];
#pragma unroll
        for (int c = 0; c < 8; ++c) wB[c] = wgp[(4 + c) * 512];
#pragma unroll
        for (int r = 0; r < 7; ++r) {
            const ulonglong2 hv = *(const ulonglong2*)&hb[r * HXROW + 0];
#pragma unroll
            for (int g = 0; g < 4; ++g) {
                ffma2(acc[g][r], wA[g].x, hv.x);
                ffma2(acc[g][r], wA[g].y, hv.y);
            }
        }

        // ---- smem planes 3..5 (hides wave B latency) ----
#pragma unroll
        for (int m = 3; m < 6; ++m) {
            const u64* bp = Wu + (2 * m) * 2048 + wbase;
            const ulonglong2 w0A = *(const ulonglong2*)(bp + h0off);
            const ulonglong2 w0B = *(const ulonglong2*)(bp + h1off);
            const ulonglong2 w1A = *(const ulonglong2*)(bp + 2048 + h0off);
            const ulonglong2 w1B = *(const ulonglong2*)(bp + 2048 + h1off);
#pragma unroll
            for (int r = 0; r < 7; ++r) {
                const ulonglong2 hv =
                    *(const ulonglong2*)&hb[r * HXROW + 12 + 4 * m];
                ffma2(acc[0][r], w0A.x, hv.x);
                ffma2(acc[1][r], w0A.y, hv.x);
                ffma2(acc[2][r], w0B.x, hv.x);
                ffma2(acc[3][r], w0B.y, hv.x);
                ffma2(acc[0][r], w1A.x, hv.y);
                ffma2(acc[1][r], w1A.y, hv.y);
                ffma2(acc[2][r], w1B.x, hv.y);
                ffma2(acc[3][r], w1B.y, hv.y);
            }
        }

        // ---- consume wave B (cc=1,2) ----
#pragma unroll
        for (int cc = 1; cc < 3; ++cc) {
#pragma unroll
            for (int r = 0; r < 7; ++r) {
                const ulonglong2 hv =
                    *(const ulonglong2*)&hb[r * HXROW + 4 * cc];
#pragma unroll
                for (int g = 0; g < 4; ++g) {
                    ffma2(acc[g][r], wB[(cc - 1) * 4 + g].x, hv.x);
                    ffma2(acc[g][r], wB[(cc - 1) * 4 + g].y, hv.y);
                }
            }
        }

        // ---- reduce across q-threads (verified parity scheme) ----
        float gvq[4], gvq4[4];
#pragma unroll
        for (int g = 0; g < 4; ++g) {
            float s[7];
#pragma unroll
            for (int p = 0; p < 7; ++p) {
                const float2 a = unpk(acc[g][p]);
                s[p] = a.x + a.y;
            }
            // level 1 (xor 1): keep rows with (p&1)==kb
#pragma unroll
            for (int sl = 0; sl < 4; ++sl) {
                const float pay = kb ? s[2 * sl]
                                     : s[(2 * sl + 1 > 6) ? 6 : 2 * sl + 1];
                const float rc = __shfl_xor_sync(0xffffffffu, pay, 1);
                s[2 * sl] += kb ? 0.0f : rc;
                if (sl < 3) s[2 * sl + 1] += kb ? rc : 0.0f;
            }
            // level 2 (xor 2)
            const float vm0 = kt ? (kb ? s[3] : s[2]) : (kb ? s[1] : s[0]);
            const float vm1 = kt ? (kb ? s[0] : s[6]) : (kb ? s[5] : s[4]);
            const float vp0 = kt ? (kb ? s[1] : s[0]) : (kb ? s[3] : s[2]);
            const float vp1 = kt ? (kb ? s[5] : s[4]) : (kb ? s[0] : s[6]);
            gvq[g]  = vm0 + __shfl_xor_sync(0xffffffffu, vp0, 2) + bias[g];
            gvq4[g] = vm1 + __shfl_xor_sync(0xffffffffu, vp1, 2) + bias[g];
        }

        // ---- activations: rows q and q+4 (q<3) ----
        {
            const float cn = sig_(gvq[1]) * c0 + sig_(gvq[0]) * tanh_(gvq[2]);
            c0 = cn;
            hn[q * HXROW + j] = sig_(gvq[3]) * tanh_(cn);
        }
        {
            const float cn = sig_(gvq4[1]) * c1 + sig_(gvq4[0]) * tanh_(gvq4[2]);
            const float hv = sig_(gvq4[3]) * tanh_(cn);
            if (q < 3) {
                c1 = cn;
                hn[(q + 4) * HXROW + j] = hv;
            }
        }
        if (doX)
            hn[xb * HXROW + 128 + xi] = xv;

        __syncthreads();
        cur ^= 1;
    }

    // ---- output: out[b] = h_T[b] . fc_w + fc_b ----
    if (tid < BB && bbase + tid < BTOT) {
        const float* hbf = hx + cur * HXBUF + tid * HXROW;
        float s = fc_b[0];
#pragma unroll 8
        for (int k = 0; k < 128; ++k) s += hbf[k] * fcw[k];
        out[bbase + tid] = s;
    }
}

extern "C" void kernel_launch(void* const* d_in, const int* in_sizes, int n_in,
                              void* d_out, int out_size)
{
    const float* x    = (const float*)d_in[0];
    const float* W_ih = (const float*)d_in[1];
    const float* W_hh = (const float*)d_in[2];
    const float* b_ih = (const float*)d_in[3];
    const float* b_hh = (const float*)d_in[4];
    const float* fc_w = (const float*)d_in[5];
    const float* fc_b = (const float*)d_in[6];
    float* out = (float*)d_out;

    cudaFuncSetAttribute(slstm_kernel,
                         cudaFuncAttributeMaxDynamicSharedMemorySize, SMEM_BYTES);
    slstm_kernel<<<NCTA, NT, SMEM_BYTES>>>(x, W_ih, W_hh, b_ih, b_hh,
                                           fc_w, fc_b, out);
}